// round 13
// baseline (speedup 1.0000x reference)
#include <cuda_runtime.h>
#include <cuda_bf16.h>
#include <math.h>
#include <stdint.h>

// ----------------------------------------------------------------------------
// Problem constants
// ----------------------------------------------------------------------------
#define BATCH   2
#define SEQ     2048
#define TOKENS  (BATCH * SEQ)        // 4096
#define DIM     2048
#define NHEAD   16
#define HEAD_DIM 128
#define FF      5632
#define QKV_LD  (3 * DIM)            // 6144

// ----------------------------------------------------------------------------
// Scratch (static device globals; no allocations allowed)
// ----------------------------------------------------------------------------
__device__ float g_xn  [(size_t)TOKENS * DIM];
__device__ float g_qkv [(size_t)TOKENS * QKV_LD];
__device__ float g_attn[(size_t)TOKENS * DIM];
__device__ float g_x1  [(size_t)TOKENS * DIM];
__device__ float g_h   [(size_t)TOKENS * FF];
// transposed weights [N, K] row-major (tf32-rounded)
__device__ float g_wTqkv[(size_t)QKV_LD * DIM];
__device__ float g_wTout[(size_t)DIM * DIM];
__device__ float g_wT13[(size_t)(2 * FF) * DIM];   // interleaved w1/w3
__device__ float g_wT2 [(size_t)DIM * FF];

// ----------------------------------------------------------------------------
// Helpers (sm_80-compatible PTX only)
// ----------------------------------------------------------------------------
__device__ __forceinline__ float tf32r(float x) {
    uint32_t r;
    asm("cvt.rna.tf32.f32 %0, %1;" : "=r"(r) : "f"(x));
    return __uint_as_float(r);
}

__device__ __forceinline__ uint32_t smem_u32(const void* p) {
    uint32_t a;
    asm("{ .reg .u64 t; cvta.to.shared.u64 t, %1; cvt.u32.u64 %0, t; }"
        : "=r"(a) : "l"(p));
    return a;
}

__device__ __forceinline__ void cp16(uint32_t dst, const void* src) {
    asm volatile("cp.async.cg.shared.global [%0], [%1], 16;"
                 :: "r"(dst), "l"(src) : "memory");
}

#define CP_COMMIT() asm volatile("cp.async.commit_group;" ::: "memory")
#define CP_WAIT(n)  asm volatile("cp.async.wait_group %0;" :: "n"(n) : "memory")

#define MMA_TF32(c, a, b) \
    asm volatile("mma.sync.aligned.m16n8k8.row.col.f32.tf32.tf32.f32 " \
        "{%0,%1,%2,%3}, {%4,%5,%6,%7}, {%8,%9}, {%0,%1,%2,%3};" \
        : "+f"((c)[0]), "+f"((c)[1]), "+f"((c)[2]), "+f"((c)[3]) \
        : "r"((a)[0]), "r"((a)[1]), "r"((a)[2]), "r"((a)[3]), \
          "r"((b)[0]), "r"((b)[1]))

// ldmatrix x4 on fp32 data viewed as b16 pairs (standard tf32 fragment trick)
#define LDSM_X4(r, addr) \
    asm volatile("ldmatrix.sync.aligned.m8n8.x4.shared.b16 {%0,%1,%2,%3}, [%4];" \
        : "=r"((r)[0]), "=r"((r)[1]), "=r"((r)[2]), "=r"((r)[3]) \
        : "r"(addr))

// fast exp2 (FMA pipe; avoids MUFU). Accurate to ~2e-7 rel.
__device__ __forceinline__ float fexp2(float x) {
    x = fminf(fmaxf(x, -126.0f), 126.0f);
    const float fl = floorf(x);
    const float f = x - fl;
    float p = 0.0018775767f;
    p = p * f + 0.0089893397f;
    p = p * f + 0.055826318f;
    p = p * f + 0.24015361f;
    p = p * f + 0.69315308f;
    p = p * f + 0.99999994f;
    const int i = (int)fl;
    return __uint_as_float((uint32_t)(i + 127) << 23) * p;
}

__device__ __forceinline__ float fsilu(float x) {
    return x / (1.0f + fexp2(-1.4426950408889634f * x));
}

// ----------------------------------------------------------------------------
// tf32 mma.sync GEMM: C[M,N] = A[M,K] @ BT[N,K]^T
//   RESID=1: C = R + A@BT^T
//   ACT=1:   interleaved (h1,h3) columns; writes silu(h1)*h3 @ pitch N/2
// BM=BN=128, BK=32, 256 threads, 3-stage cp.async, ldmatrix fragment loads.
// GROUP_N=8 rasterization; __launch_bounds__(256,2).
// ----------------------------------------------------------------------------
#define SLD 36                        // smem row pitch (floats) -> 144B
#define BUF_FLOATS (128 * SLD)
#define GEMM_SMEM (6 * BUF_FLOATS * 4)   // 110592 bytes
#define GROUP_N 8

template <int RESID, int ACT>
__global__ void __launch_bounds__(256, 2) mma_gemm(
    const float* __restrict__ A, const float* __restrict__ BT,
    const float* __restrict__ R, float* __restrict__ C,
    int M, int N, int K)
{
    extern __shared__ float sm[];
    const uint32_t sbase = smem_u32(sm);

    const int tid  = threadIdx.x;
    const int lane = tid & 31;
    const int wid  = tid >> 5;
    const int warpM = wid & 1;
    const int warpN = wid >> 1;

    const int num_bm = M >> 7;
    const int pid = blockIdx.x;
    const int gsz = GROUP_N * num_bm;
    const int first_bn = (pid / gsz) * GROUP_N;
    const int rem = pid % gsz;
    const int bn = first_bn + (rem & (GROUP_N - 1));
    const int bm = rem >> 3;

    const float* Ab = A  + (size_t)bm * 128 * K;
    const float* Bb = BT + (size_t)bn * 128 * K;

    float c[4][4][4];
    #pragma unroll
    for (int mt = 0; mt < 4; mt++)
        #pragma unroll
        for (int nt = 0; nt < 4; nt++)
            #pragma unroll
            for (int j = 0; j < 4; j++) c[mt][nt][j] = 0.0f;

    auto issue_tile = [&](int t, int s) {
        const float* Agt = Ab + t * 32;
        const float* Bgt = Bb + t * 32;
        const uint32_t baseA = sbase + (uint32_t)s * 2u * 18432u;
        const uint32_t baseB = baseA + 18432u;
        #pragma unroll
        for (int i = 0; i < 4; i++) {
            const int idx = tid + i * 256;
            const int rr = idx >> 3;
            const int c4 = idx & 7;
            const uint32_t off = (uint32_t)(rr * SLD + c4 * 4) * 4u;
            cp16(baseA + off, Agt + (size_t)rr * K + c4 * 4);
            cp16(baseB + off, Bgt + (size_t)rr * K + c4 * 4);
        }
        CP_COMMIT();
    };

    const int lm = lane >> 3;
    const int lj = lane & 7;
    const uint32_t a_row = (uint32_t)(warpM * 64 + (lm & 1) * 8 + lj);
    const uint32_t a_col = (uint32_t)((lm >> 1) * 4);
    const uint32_t b_row = (uint32_t)(warpN * 32 + (lm >> 1) * 8 + lj);
    const uint32_t b_col = (uint32_t)((lm & 1) * 4);

    auto compute_tile = [&](int s) {
        const uint32_t Ash = sbase + (uint32_t)s * 2u * 18432u;
        const uint32_t Bsh = Ash + 18432u;
        const uint32_t aaddr0 = Ash + (a_row * SLD + a_col) * 4u;
        const uint32_t baddr0 = Bsh + (b_row * SLD + b_col) * 4u;
        #pragma unroll
        for (int kk = 0; kk < 32; kk += 8) {
            uint32_t a[4][4], b[2][4];
            #pragma unroll
            for (int mt = 0; mt < 4; mt++)
                LDSM_X4(a[mt], aaddr0 + (uint32_t)(mt * 16 * SLD + kk) * 4u);
            #pragma unroll
            for (int np = 0; np < 2; np++)
                LDSM_X4(b[np], baddr0 + (uint32_t)(np * 16 * SLD + kk) * 4u);
            #pragma unroll
            for (int mt = 0; mt < 4; mt++) {
                #pragma unroll
                for (int np = 0; np < 2; np++) {
                    MMA_TF32(c[mt][2 * np],     a[mt], &b[np][0]);
                    MMA_TF32(c[mt][2 * np + 1], a[mt], &b[np][2]);
                }
            }
        }
    };

    const int NT = K / 32;
    issue_tile(0, 0);
    issue_tile(1, 1);
    int s = 0;
    for (int t = 0; t < NT; t++) {
        if (t + 1 < NT) { CP_WAIT(1); } else { CP_WAIT(0); }
        __syncthreads();
        if (t + 2 < NT) {
            int s2 = s + 2; if (s2 >= 3) s2 -= 3;
            issue_tile(t + 2, s2);
        }
        compute_tile(s);
        if (++s == 3) s = 0;
    }

    if (ACT) {
        const int No = N >> 1;
        #pragma unroll
        for (int mt = 0; mt < 4; mt++) {
            const int r0 = bm * 128 + warpM * 64 + mt * 16 + (lane >> 2);
            #pragma unroll
            for (int nt = 0; nt < 4; nt++) {
                const int ocol = (bn * 128 + warpN * 32 + nt * 8) / 2 + (lane & 3);
                C[(size_t)r0 * No + ocol] =
                    tf32r(fsilu(c[mt][nt][0]) * c[mt][nt][1]);
                C[(size_t)(r0 + 8) * No + ocol] =
                    tf32r(fsilu(c[mt][nt][2]) * c[mt][nt][3]);
            }
        }
    } else {
        #pragma unroll
        for (int mt = 0; mt < 4; mt++) {
            const int r0 = bm * 128 + warpM * 64 + mt * 16 + (lane >> 2);
            #pragma unroll
            for (int nt = 0; nt < 4; nt++) {
                const int col = bn * 128 + warpN * 32 + nt * 8 + (lane & 3) * 2;
                const size_t i0 = (size_t)r0 * N + col;
                const size_t i1 = i0 + (size_t)8 * N;
                float2 v0 = make_float2(c[mt][nt][0], c[mt][nt][1]);
                float2 v1 = make_float2(c[mt][nt][2], c[mt][nt][3]);
                if (RESID) {
                    const float2 r0v = *(const float2*)(R + i0);
                    const float2 r1v = *(const float2*)(R + i1);
                    v0.x += r0v.x; v0.y += r0v.y;
                    v1.x += r1v.x; v1.y += r1v.y;
                }
                *(float2*)(C + i0) = v0;
                *(float2*)(C + i1) = v1;
            }
        }
    }
}

// ----------------------------------------------------------------------------
// Weight transpose: in[Kd,Nd] -> out[(rstride*n + roff), Kd], tf32-rounded
// ----------------------------------------------------------------------------
__global__ void __launch_bounds__(256) transpose_kernel(
    const float* __restrict__ in, float* __restrict__ out, int Kd, int Nd,
    int rstride, int roff)
{
    __shared__ float t[32][33];
    const int n0 = blockIdx.x * 32;
    const int k0 = blockIdx.y * 32;
    const int x = threadIdx.x & 31;
    const int y = threadIdx.x >> 5;
    #pragma unroll
    for (int i = 0; i < 4; i++)
        t[y + i * 8][x] = in[(size_t)(k0 + y + i * 8) * Nd + n0 + x];
    __syncthreads();
    #pragma unroll
    for (int i = 0; i < 4; i++)
        out[(size_t)(rstride * (n0 + y + i * 8) + roff) * Kd + k0 + x]
            = tf32r(t[x][y + i * 8]);
}

// ----------------------------------------------------------------------------
// RMSNorm: one block per row; output rounded to tf32 (feeds GEMMs)
// ----------------------------------------------------------------------------
__global__ void __launch_bounds__(256) rmsnorm_kernel(
    const float* __restrict__ x, const float* __restrict__ g, float* __restrict__ y)
{
    __shared__ float red[8];
    const int row = blockIdx.x;
    const int t = threadIdx.x;
    const float4* xr = (const float4*)(x + (size_t)row * DIM);
    const float4* gr = (const float4*)g;
    float4* yr = (float4*)(y + (size_t)row * DIM);

    float4 v0 = xr[t];
    float4 v1 = xr[t + 256];
    float ss = v0.x*v0.x + v0.y*v0.y + v0.z*v0.z + v0.w*v0.w
             + v1.x*v1.x + v1.y*v1.y + v1.z*v1.z + v1.w*v1.w;
    #pragma unroll
    for (int m = 16; m > 0; m >>= 1) ss += __shfl_xor_sync(0xffffffffu, ss, m);
    if ((t & 31) == 0) red[t >> 5] = ss;
    __syncthreads();
    float tot = red[0] + red[1] + red[2] + red[3] + red[4] + red[5] + red[6] + red[7];
    float inv = rsqrtf(tot * (1.0f / (float)DIM) + 1e-6f);

    float4 g0 = gr[t], g1v = gr[t + 256];
    float4 o0, o1;
    o0.x = tf32r(v0.x * inv * g0.x);  o0.y = tf32r(v0.y * inv * g0.y);
    o0.z = tf32r(v0.z * inv * g0.z);  o0.w = tf32r(v0.w * inv * g0.w);
    o1.x = tf32r(v1.x * inv * g1v.x); o1.y = tf32r(v1.y * inv * g1v.y);
    o1.z = tf32r(v1.z * inv * g1v.z); o1.w = tf32r(v1.w * inv * g1v.w);
    yr[t] = o0;
    yr[t + 256] = o1;
}

// ----------------------------------------------------------------------------
// Tensor-core flash attention, tf32 mma.sync, causal.
// BM=64, BN=64, D=128, 128 threads (4 warps), single KV buffer, 2 CTAs/SM.
// Q fragments hoisted to registers.
// V stored fragment-friendly: col = a + 16*b for dim n = 8a+b, pitch 136.
// PV B-fragments then read as float4s (64 LDS.128/tile vs 256 scalar LDS).
// ----------------------------------------------------------------------------
#define AQ_LD 132
#define AK_LD 132
#define AV_LD 136
#define AP_LD 68
#define KV_FLOATS (64 * AK_LD + 64 * AV_LD)     // 17152
#define ATTN3_SMEM ((KV_FLOATS + 64 * AP_LD) * 4)   // 86016 bytes

__global__ void __launch_bounds__(128) attn_mma_kernel(
    const float* __restrict__ qkv, float* __restrict__ out)
{
    extern __shared__ float sm[];
    const uint32_t sb = smem_u32(sm);
    float* Vs2 = sm + 64 * AK_LD;          // V region (pitch AV_LD)
    float* Ps = sm + KV_FLOATS;
    const uint32_t Psb = sb + (uint32_t)KV_FLOATS * 4u;

    const int qb = 31 - (int)blockIdx.x;   // long blocks first
    const int h = blockIdx.y;
    const int b = blockIdx.z;
    const int tid = threadIdx.x;
    const int lane = tid & 31;
    const int wid = tid >> 5;              // 0..3
    const int g = lane >> 2;
    const int q = lane & 3;
    const int wrow = wid * 16;
    const int q0 = qb * 64;
    const size_t base = (size_t)b * SEQ * QKV_LD;
    const float qscale = 0.08838834764831845f * 1.4426950408889634f;

    const int lm = lane >> 3;
    const int lj = lane & 7;

    // ---- prologue: stage Q (64x128) through KV region, hoist frags to regs ----
    #pragma unroll
    for (int i = 0; i < 16; i++) {
        const int idx = tid + i * 128;      // 0..2047
        const int r = idx >> 5;
        const int c = (idx & 31) << 2;
        const float4 v = *(const float4*)&qkv[base + (size_t)(q0 + r) * QKV_LD
                                              + h * HEAD_DIM + c];
        float* dst = &sm[r * AQ_LD + c];
        dst[0] = tf32r(v.x * qscale);
        dst[1] = tf32r(v.y * qscale);
        dst[2] = tf32r(v.z * qscale);
        dst[3] = tf32r(v.w * qscale);
    }
    __syncthreads();

    uint32_t Qf[16][4];
    {
        const uint32_t qa_addr0 = sb
            + ((uint32_t)(wrow + (lm & 1) * 8 + lj) * AQ_LD + (lm >> 1) * 4) * 4u;
        #pragma unroll
        for (int kt = 0; kt < 16; kt++)
            LDSM_X4(Qf[kt], qa_addr0 + (uint32_t)(kt * 8) * 4u);
    }
    __syncthreads();   // KV region free now

    const uint32_t pa_addr0 = Psb
        + ((uint32_t)(wrow + (lm & 1) * 8 + lj) * AP_LD + (lm >> 1) * 4) * 4u;
    const uint32_t kb_addr0 = sb
        + ((uint32_t)((lm >> 1) * 8 + lj) * AK_LD + (lm & 1) * 4) * 4u;

    float mreg[2] = {-1e5f, -1e5f};
    float lreg[2] = {0.0f, 0.0f};
    float O[16][4];
    #pragma unroll
    for (int nt = 0; nt < 16; nt++)
        #pragma unroll
        for (int j = 0; j < 4; j++) O[nt][j] = 0.0f;

    const int ntiles = qb + 1;
    for (int jb = 0; jb < ntiles; jb++) {
        const int k0 = jb * 64;
        // ---- K tile via cp.async: 64 rows x 32 quads = 2048 cp16 ----
        #pragma unroll
        for (int i = 0; i < 16; i++) {
            const int idx = tid + i * 128;  // 0..2047
            const int r = idx >> 5;         // 0..63
            const int c4 = (idx & 31) * 4;
            const float* src = &qkv[base + (size_t)(k0 + r) * QKV_LD
                                    + DIM + h * HEAD_DIM + c4];
            cp16(sb + (uint32_t)(r * AK_LD + c4) * 4u, src);
        }
        CP_COMMIT();

        // ---- V tile via LDG + swizzled STS: col = a + 16*b for n = 8a+b ----
        #pragma unroll
        for (int i = 0; i < 8; i++) {
            const int idx = tid + i * 128;  // 0..1023
            const int r = idx >> 4;         // key row 0..63
            const int l = idx & 15;         // dim octet 0..15
            const float* sv = &qkv[base + (size_t)(k0 + r) * QKV_LD
                                   + 2 * DIM + h * HEAD_DIM + 8 * l];
            const float4 v0 = *(const float4*)sv;
            const float4 v1 = *(const float4*)(sv + 4);
            float* vr = Vs2 + r * AV_LD + l;
            vr[0]   = v0.x;  vr[16]  = v0.y;  vr[32]  = v0.z;  vr[48]  = v0.w;
            vr[64]  = v1.x;  vr[80]  = v1.y;  vr[96]  = v1.z;  vr[112] = v1.w;
        }
        CP_WAIT(0);
        __syncthreads();

        // ---- S = Q K^T ----
        float sreg[8][4];
        #pragma unroll
        for (int nt = 0; nt < 8; nt++)
            #pragma unroll
            for (int j = 0; j < 4; j++) sreg[nt][j] = 0.0f;

        #pragma unroll
        for (int kt = 0; kt < 16; kt++) {
            uint32_t bk[4][4];
            #pragma unroll
            for (int np = 0; np < 4; np++)
                LDSM_X4(bk[np], kb_addr0
                        + (uint32_t)(np * 16 * AK_LD + kt * 8) * 4u);
            #pragma unroll
            for (int np = 0; np < 4; np++) {
                MMA_TF32(sreg[2 * np],     Qf[kt], &bk[np][0]);
                MMA_TF32(sreg[2 * np + 1], Qf[kt], &bk[np][2]);
            }
        }

        // ---- online softmax (base-2; scale folded into Q) ----
        const bool need_mask = (jb == qb);
        #pragma unroll
        for (int hh = 0; hh < 2; hh++) {
            const int row = q0 + wrow + g + hh * 8;
            if (need_mask) {
                #pragma unroll
                for (int nt = 0; nt < 8; nt++) {
                    const int col = k0 + nt * 8 + 2 * q;
                    if (col > row)     sreg[nt][2 * hh]     = -1e30f;
                    if (col + 1 > row) sreg[nt][2 * hh + 1] = -1e30f;
                }
            }
            float rmax = -1e30f;
            #pragma unroll
            for (int nt = 0; nt < 8; nt++)
                rmax = fmaxf(rmax, fmaxf(sreg[nt][2 * hh], sreg[nt][2 * hh + 1]));
            rmax = fmaxf(rmax, __shfl_xor_sync(0xffffffffu, rmax, 1));
            rmax = fmaxf(rmax, __shfl_xor_sync(0xffffffffu, rmax, 2));

            const float mnew = fmaxf(mreg[hh], rmax);
            const float corr = fexp2(mreg[hh] - mnew);
            float rsum = 0.0f;
            #pragma unroll
            for (int nt = 0; nt < 8; nt++) {
                const float p0 = fexp2(sreg[nt][2 * hh]     - mnew);
                const float p1 = fexp2(sreg[nt][2 * hh + 1] - mnew);
                sreg[nt][2 * hh] = p0;
                sreg[nt][2 * hh + 1] = p1;
                rsum += p0 + p1;
            }
            rsum += __shfl_xor_sync(0xffffffffu, rsum, 1);
            rsum += __shfl_xor_sync(0xffffffffu, rsum, 2);
            lreg[hh] = lreg[hh] * corr + rsum;
            mreg[hh] = mnew;
            #pragma unroll
            for (int nt2 = 0; nt2 < 16; nt2++) {
                O[nt2][2 * hh] *= corr;
                O[nt2][2 * hh + 1] *= corr;
            }
            #pragma unroll
            for (int nt = 0; nt < 8; nt++) {
                float2 pv = make_float2(tf32r(sreg[nt][2 * hh]),
                                        tf32r(sreg[nt][2 * hh + 1]));
                *(float2*)&Ps[(wrow + g + hh * 8) * AP_LD + nt * 8 + 2 * q] = pv;
            }
        }
        __syncwarp();

        // ---- O += P V  (vectorized V fragment loads) ----
        #pragma unroll
        for (int kt2 = 0; kt2 < 8; kt2++) {
            uint32_t a[4];
            LDSM_X4(a, pa_addr0 + (uint32_t)(kt2 * 8) * 4u);
            const float* Va = Vs2 + (kt2 * 8 + q) * AV_LD + 16 * g;
            const float* Vb = Va + 4 * AV_LD;
            float va[16], vb[16];
            #pragma unroll
            for (int t4 = 0; t4 < 4; t4++) {
                *(float4*)&va[t4 * 4] = *(const float4*)(Va + 4 * t4);
                *(float4*)&vb[t4 * 4] = *(const float4*)(Vb + 4 * t4);
            }
            #pragma unroll
            for (int nt2 = 0; nt2 < 16; nt2++) {
                uint32_t bfr[2];
                bfr[0] = __float_as_uint(va[nt2]);
                bfr[1] = __float_as_uint(vb[nt2]);
                MMA_TF32(O[nt2], a, bfr);
            }
        }
        __syncthreads();   // all warps done with K/V before next overwrite
    }

    // epilogue: normalize + store (tf32-rounded; feeds out-proj GEMM)
    #pragma unroll
    for (int hh = 0; hh < 2; hh++) {
        const float inv = 1.0f / lreg[hh];
        const int row = q0 + wrow + g + hh * 8;
        float* orow = out + ((size_t)(b * SEQ + row)) * DIM + h * HEAD_DIM;
        #pragma unroll
        for (int nt2 = 0; nt2 < 16; nt2++) {
            float2 v = make_float2(tf32r(O[nt2][2 * hh] * inv),
                                   tf32r(O[nt2][2 * hh + 1] * inv));
            *(float2*)&orow[nt2 * 8 + 2 * q] = v;
        }
    }
}

// ----------------------------------------------------------------------------
// Launch
// ----------------------------------------------------------------------------
extern "C" void kernel_launch(void* const* d_in, const int* in_sizes, int n_in,
                              void* d_out, int out_size)
{
    const float* x     = (const float*)d_in[0];
    const float* w_qkv = (const float*)d_in[1];
    const float* w_out = (const float*)d_in[2];
    const float* g1    = (const float*)d_in[3];
    const float* g2    = (const float*)d_in[4];
    const float* w1    = (const float*)d_in[5];
    const float* w3    = (const float*)d_in[6];
    const float* w2    = (const float*)d_in[7];
    float* out = (float*)d_out;

    float *xn, *qkvb, *attnb, *x1, *h;
    float *wTqkv, *wTout, *wT13, *wT2;
    cudaGetSymbolAddress((void**)&xn,    g_xn);
    cudaGetSymbolAddress((void**)&qkvb,  g_qkv);
    cudaGetSymbolAddress((void**)&attnb, g_attn);
    cudaGetSymbolAddress((void**)&x1,    g_x1);
    cudaGetSymbolAddress((void**)&h,     g_h);
    cudaGetSymbolAddress((void**)&wTqkv, g_wTqkv);
    cudaGetSymbolAddress((void**)&wTout, g_wTout);
    cudaGetSymbolAddress((void**)&wT13,  g_wT13);
    cudaGetSymbolAddress((void**)&wT2,   g_wT2);

    cudaFuncSetAttribute(attn_mma_kernel,
                         cudaFuncAttributeMaxDynamicSharedMemorySize, ATTN3_SMEM);
    cudaFuncSetAttribute(mma_gemm<0,0>,
                         cudaFuncAttributeMaxDynamicSharedMemorySize, GEMM_SMEM);
    cudaFuncSetAttribute(mma_gemm<1,0>,
                         cudaFuncAttributeMaxDynamicSharedMemorySize, GEMM_SMEM);
    cudaFuncSetAttribute(mma_gemm<0,1>,
                         cudaFuncAttributeMaxDynamicSharedMemorySize, GEMM_SMEM);

    transpose_kernel<<<dim3(QKV_LD / 32, DIM / 32), 256>>>(w_qkv, wTqkv, DIM, QKV_LD, 1, 0);
    rmsnorm_kernel<<<TOKENS, 256>>>(x, g1, xn);
    mma_gemm<0,0><<<(QKV_LD / 128) * (TOKENS / 128), 256, GEMM_SMEM>>>(
        xn, wTqkv, (const float*)0, qkvb, TOKENS, QKV_LD, DIM);
    attn_mma_kernel<<<dim3(SEQ / 64, NHEAD, BATCH), 128, ATTN3_SMEM>>>(qkvb, attnb);
    transpose_kernel<<<dim3(DIM / 32, DIM / 32), 256>>>(w_out, wTout, DIM, DIM, 1, 0);
    mma_gemm<1,0><<<(DIM / 128) * (TOKENS / 128), 256, GEMM_SMEM>>>(
        attnb, wTout, x, x1, TOKENS, DIM, DIM);
    rmsnorm_kernel<<<TOKENS, 256>>>(x1, g2, xn);
    transpose_kernel<<<dim3(FF / 32, DIM / 32), 256>>>(w1, wT13, DIM, FF, 2, 0);
    transpose_kernel<<<dim3(FF / 32, DIM / 32), 256>>>(w3, wT13, DIM, FF, 2, 1);
    mma_gemm<0,1><<<(2 * FF / 128) * (TOKENS / 128), 256, GEMM_SMEM>>>(
        xn, wT13, (const float*)0, h, TOKENS, 2 * FF, DIM);
    transpose_kernel<<<dim3(DIM / 32, FF / 32), 256>>>(w2, wT2, FF, DIM, 1, 0);
    mma_gemm<1,0><<<(DIM / 128) * (TOKENS / 128), 256, GEMM_SMEM>>>(
        h, wT2, x1, out, TOKENS, DIM, FF);
}

// round 14
// speedup vs baseline: 1.0464x; 1.0464x over previous
#include <cuda_runtime.h>
#include <cuda_bf16.h>
#include <math.h>
#include <stdint.h>

// ----------------------------------------------------------------------------
// Problem constants
// ----------------------------------------------------------------------------
#define BATCH   2
#define SEQ     2048
#define TOKENS  (BATCH * SEQ)        // 4096
#define DIM     2048
#define NHEAD   16
#define HEAD_DIM 128
#define FF      5632
#define QKV_LD  (3 * DIM)            // 6144

// ----------------------------------------------------------------------------
// Scratch (static device globals; no allocations allowed)
// ----------------------------------------------------------------------------
__device__ float g_xn  [(size_t)TOKENS * DIM];
__device__ float g_qkv [(size_t)TOKENS * QKV_LD];
__device__ float g_attn[(size_t)TOKENS * DIM];
__device__ float g_x1  [(size_t)TOKENS * DIM];
__device__ float g_h   [(size_t)TOKENS * FF];
// transposed weights [N, K] row-major (tf32-rounded)
__device__ float g_wTqkv[(size_t)QKV_LD * DIM];
__device__ float g_wTout[(size_t)DIM * DIM];
__device__ float g_wT13[(size_t)(2 * FF) * DIM];   // interleaved w1/w3
__device__ float g_wT2 [(size_t)DIM * FF];

// ----------------------------------------------------------------------------
// Helpers (sm_80-compatible PTX only)
// ----------------------------------------------------------------------------
__device__ __forceinline__ float tf32r(float x) {
    uint32_t r;
    asm("cvt.rna.tf32.f32 %0, %1;" : "=r"(r) : "f"(x));
    return __uint_as_float(r);
}

__device__ __forceinline__ uint32_t smem_u32(const void* p) {
    uint32_t a;
    asm("{ .reg .u64 t; cvta.to.shared.u64 t, %1; cvt.u32.u64 %0, t; }"
        : "=r"(a) : "l"(p));
    return a;
}

__device__ __forceinline__ void cp16(uint32_t dst, const void* src) {
    asm volatile("cp.async.cg.shared.global [%0], [%1], 16;"
                 :: "r"(dst), "l"(src) : "memory");
}

#define CP_COMMIT() asm volatile("cp.async.commit_group;" ::: "memory")
#define CP_WAIT(n)  asm volatile("cp.async.wait_group %0;" :: "n"(n) : "memory")

#define MMA_TF32(c, a, b) \
    asm volatile("mma.sync.aligned.m16n8k8.row.col.f32.tf32.tf32.f32 " \
        "{%0,%1,%2,%3}, {%4,%5,%6,%7}, {%8,%9}, {%0,%1,%2,%3};" \
        : "+f"((c)[0]), "+f"((c)[1]), "+f"((c)[2]), "+f"((c)[3]) \
        : "r"((a)[0]), "r"((a)[1]), "r"((a)[2]), "r"((a)[3]), \
          "r"((b)[0]), "r"((b)[1]))

// ldmatrix x4 on fp32 data viewed as b16 pairs (standard tf32 fragment trick)
#define LDSM_X4(r, addr) \
    asm volatile("ldmatrix.sync.aligned.m8n8.x4.shared.b16 {%0,%1,%2,%3}, [%4];" \
        : "=r"((r)[0]), "=r"((r)[1]), "=r"((r)[2]), "=r"((r)[3]) \
        : "r"(addr))

// fast exp2 (FMA pipe; avoids MUFU). Accurate to ~2e-7 rel.
__device__ __forceinline__ float fexp2(float x) {
    x = fminf(fmaxf(x, -126.0f), 126.0f);
    const float fl = floorf(x);
    const float f = x - fl;
    float p = 0.0018775767f;
    p = p * f + 0.0089893397f;
    p = p * f + 0.055826318f;
    p = p * f + 0.24015361f;
    p = p * f + 0.69315308f;
    p = p * f + 0.99999994f;
    const int i = (int)fl;
    return __uint_as_float((uint32_t)(i + 127) << 23) * p;
}

__device__ __forceinline__ float fsilu(float x) {
    return x / (1.0f + fexp2(-1.4426950408889634f * x));
}

// ----------------------------------------------------------------------------
// tf32 mma.sync GEMM: C[M,N] = A[M,K] @ BT[N,K]^T
//   RESID=1: C = R + A@BT^T
//   ACT=1:   interleaved (h1,h3) columns; writes silu(h1)*h3 @ pitch N/2
// BM=BN=128, BK=32, 256 threads, 3-stage cp.async, ldmatrix fragment loads.
// GROUP_N=8 rasterization; __launch_bounds__(256,2).
// ----------------------------------------------------------------------------
#define SLD 36                        // smem row pitch (floats) -> 144B
#define BUF_FLOATS (128 * SLD)
#define GEMM_SMEM (6 * BUF_FLOATS * 4)   // 110592 bytes
#define GROUP_N 8

template <int RESID, int ACT>
__global__ void __launch_bounds__(256, 2) mma_gemm(
    const float* __restrict__ A, const float* __restrict__ BT,
    const float* __restrict__ R, float* __restrict__ C,
    int M, int N, int K)
{
    extern __shared__ float sm[];
    const uint32_t sbase = smem_u32(sm);

    const int tid  = threadIdx.x;
    const int lane = tid & 31;
    const int wid  = tid >> 5;
    const int warpM = wid & 1;
    const int warpN = wid >> 1;

    const int num_bm = M >> 7;
    const int pid = blockIdx.x;
    const int gsz = GROUP_N * num_bm;
    const int first_bn = (pid / gsz) * GROUP_N;
    const int rem = pid % gsz;
    const int bn = first_bn + (rem & (GROUP_N - 1));
    const int bm = rem >> 3;

    const float* Ab = A  + (size_t)bm * 128 * K;
    const float* Bb = BT + (size_t)bn * 128 * K;

    float c[4][4][4];
    #pragma unroll
    for (int mt = 0; mt < 4; mt++)
        #pragma unroll
        for (int nt = 0; nt < 4; nt++)
            #pragma unroll
            for (int j = 0; j < 4; j++) c[mt][nt][j] = 0.0f;

    auto issue_tile = [&](int t, int s) {
        const float* Agt = Ab + t * 32;
        const float* Bgt = Bb + t * 32;
        const uint32_t baseA = sbase + (uint32_t)s * 2u * 18432u;
        const uint32_t baseB = baseA + 18432u;
        #pragma unroll
        for (int i = 0; i < 4; i++) {
            const int idx = tid + i * 256;
            const int rr = idx >> 3;
            const int c4 = idx & 7;
            const uint32_t off = (uint32_t)(rr * SLD + c4 * 4) * 4u;
            cp16(baseA + off, Agt + (size_t)rr * K + c4 * 4);
            cp16(baseB + off, Bgt + (size_t)rr * K + c4 * 4);
        }
        CP_COMMIT();
    };

    const int lm = lane >> 3;
    const int lj = lane & 7;
    const uint32_t a_row = (uint32_t)(warpM * 64 + (lm & 1) * 8 + lj);
    const uint32_t a_col = (uint32_t)((lm >> 1) * 4);
    const uint32_t b_row = (uint32_t)(warpN * 32 + (lm >> 1) * 8 + lj);
    const uint32_t b_col = (uint32_t)((lm & 1) * 4);

    auto compute_tile = [&](int s) {
        const uint32_t Ash = sbase + (uint32_t)s * 2u * 18432u;
        const uint32_t Bsh = Ash + 18432u;
        const uint32_t aaddr0 = Ash + (a_row * SLD + a_col) * 4u;
        const uint32_t baddr0 = Bsh + (b_row * SLD + b_col) * 4u;
        #pragma unroll
        for (int kk = 0; kk < 32; kk += 8) {
            uint32_t a[4][4], b[2][4];
            #pragma unroll
            for (int mt = 0; mt < 4; mt++)
                LDSM_X4(a[mt], aaddr0 + (uint32_t)(mt * 16 * SLD + kk) * 4u);
            #pragma unroll
            for (int np = 0; np < 2; np++)
                LDSM_X4(b[np], baddr0 + (uint32_t)(np * 16 * SLD + kk) * 4u);
            #pragma unroll
            for (int mt = 0; mt < 4; mt++) {
                #pragma unroll
                for (int np = 0; np < 2; np++) {
                    MMA_TF32(c[mt][2 * np],     a[mt], &b[np][0]);
                    MMA_TF32(c[mt][2 * np + 1], a[mt], &b[np][2]);
                }
            }
        }
    };

    const int NT = K / 32;
    issue_tile(0, 0);
    issue_tile(1, 1);
    int s = 0;
    for (int t = 0; t < NT; t++) {
        if (t + 1 < NT) { CP_WAIT(1); } else { CP_WAIT(0); }
        __syncthreads();
        if (t + 2 < NT) {
            int s2 = s + 2; if (s2 >= 3) s2 -= 3;
            issue_tile(t + 2, s2);
        }
        compute_tile(s);
        if (++s == 3) s = 0;
    }

    if (ACT) {
        const int No = N >> 1;
        #pragma unroll
        for (int mt = 0; mt < 4; mt++) {
            const int r0 = bm * 128 + warpM * 64 + mt * 16 + (lane >> 2);
            #pragma unroll
            for (int nt = 0; nt < 4; nt++) {
                const int ocol = (bn * 128 + warpN * 32 + nt * 8) / 2 + (lane & 3);
                C[(size_t)r0 * No + ocol] =
                    tf32r(fsilu(c[mt][nt][0]) * c[mt][nt][1]);
                C[(size_t)(r0 + 8) * No + ocol] =
                    tf32r(fsilu(c[mt][nt][2]) * c[mt][nt][3]);
            }
        }
    } else {
        #pragma unroll
        for (int mt = 0; mt < 4; mt++) {
            const int r0 = bm * 128 + warpM * 64 + mt * 16 + (lane >> 2);
            #pragma unroll
            for (int nt = 0; nt < 4; nt++) {
                const int col = bn * 128 + warpN * 32 + nt * 8 + (lane & 3) * 2;
                const size_t i0 = (size_t)r0 * N + col;
                const size_t i1 = i0 + (size_t)8 * N;
                float2 v0 = make_float2(c[mt][nt][0], c[mt][nt][1]);
                float2 v1 = make_float2(c[mt][nt][2], c[mt][nt][3]);
                if (RESID) {
                    const float2 r0v = *(const float2*)(R + i0);
                    const float2 r1v = *(const float2*)(R + i1);
                    v0.x += r0v.x; v0.y += r0v.y;
                    v1.x += r1v.x; v1.y += r1v.y;
                }
                *(float2*)(C + i0) = v0;
                *(float2*)(C + i1) = v1;
            }
        }
    }
}

// ----------------------------------------------------------------------------
// Weight transpose: in[Kd,Nd] -> out[(rstride*n + roff), Kd], tf32-rounded
// ----------------------------------------------------------------------------
__global__ void __launch_bounds__(256) transpose_kernel(
    const float* __restrict__ in, float* __restrict__ out, int Kd, int Nd,
    int rstride, int roff)
{
    __shared__ float t[32][33];
    const int n0 = blockIdx.x * 32;
    const int k0 = blockIdx.y * 32;
    const int x = threadIdx.x & 31;
    const int y = threadIdx.x >> 5;
    #pragma unroll
    for (int i = 0; i < 4; i++)
        t[y + i * 8][x] = in[(size_t)(k0 + y + i * 8) * Nd + n0 + x];
    __syncthreads();
    #pragma unroll
    for (int i = 0; i < 4; i++)
        out[(size_t)(rstride * (n0 + y + i * 8) + roff) * Kd + k0 + x]
            = tf32r(t[x][y + i * 8]);
}

// ----------------------------------------------------------------------------
// RMSNorm: one block per row; output rounded to tf32 (feeds GEMMs)
// ----------------------------------------------------------------------------
__global__ void __launch_bounds__(256) rmsnorm_kernel(
    const float* __restrict__ x, const float* __restrict__ g, float* __restrict__ y)
{
    __shared__ float red[8];
    const int row = blockIdx.x;
    const int t = threadIdx.x;
    const float4* xr = (const float4*)(x + (size_t)row * DIM);
    const float4* gr = (const float4*)g;
    float4* yr = (float4*)(y + (size_t)row * DIM);

    float4 v0 = xr[t];
    float4 v1 = xr[t + 256];
    float ss = v0.x*v0.x + v0.y*v0.y + v0.z*v0.z + v0.w*v0.w
             + v1.x*v1.x + v1.y*v1.y + v1.z*v1.z + v1.w*v1.w;
    #pragma unroll
    for (int m = 16; m > 0; m >>= 1) ss += __shfl_xor_sync(0xffffffffu, ss, m);
    if ((t & 31) == 0) red[t >> 5] = ss;
    __syncthreads();
    float tot = red[0] + red[1] + red[2] + red[3] + red[4] + red[5] + red[6] + red[7];
    float inv = rsqrtf(tot * (1.0f / (float)DIM) + 1e-6f);

    float4 g0 = gr[t], g1v = gr[t + 256];
    float4 o0, o1;
    o0.x = tf32r(v0.x * inv * g0.x);  o0.y = tf32r(v0.y * inv * g0.y);
    o0.z = tf32r(v0.z * inv * g0.z);  o0.w = tf32r(v0.w * inv * g0.w);
    o1.x = tf32r(v1.x * inv * g1v.x); o1.y = tf32r(v1.y * inv * g1v.y);
    o1.z = tf32r(v1.z * inv * g1v.z); o1.w = tf32r(v1.w * inv * g1v.w);
    yr[t] = o0;
    yr[t + 256] = o1;
}

// ----------------------------------------------------------------------------
// Tensor-core flash attention, tf32 mma.sync, causal.
// BM=64, BN=64, D=128, 128 threads (4 warps), single KV buffer, 2 CTAs/SM.
// Q fragments hoisted to registers.
// Phase-pipelined loads: K(jb+1) issued during softmax/PV of jb (K region
// free after S); V(jb+1) issued after PV. FIFO wait_group separates them.
// ----------------------------------------------------------------------------
#define AQ_LD 132
#define AK_LD 132
#define AV_LD 136
#define AP_LD 68
#define KV_FLOATS (64 * AK_LD + 64 * AV_LD)     // 17152
#define ATTN3_SMEM ((KV_FLOATS + 64 * AP_LD) * 4)   // 86016 bytes

__global__ void __launch_bounds__(128) attn_mma_kernel(
    const float* __restrict__ qkv, float* __restrict__ out)
{
    extern __shared__ float sm[];
    const uint32_t sb = smem_u32(sm);
    float* Ps = sm + KV_FLOATS;
    const uint32_t Psb = sb + (uint32_t)KV_FLOATS * 4u;

    const int qb = 31 - (int)blockIdx.x;   // long blocks first
    const int h = blockIdx.y;
    const int b = blockIdx.z;
    const int tid = threadIdx.x;
    const int lane = tid & 31;
    const int wid = tid >> 5;              // 0..3
    const int g = lane >> 2;
    const int q = lane & 3;
    const int wrow = wid * 16;
    const int q0 = qb * 64;
    const size_t base = (size_t)b * SEQ * QKV_LD;
    const float qscale = 0.08838834764831845f * 1.4426950408889634f;

    const int lm = lane >> 3;
    const int lj = lane & 7;

    // ---- prologue: stage Q (64x128) through KV region, hoist frags to regs ----
    #pragma unroll
    for (int i = 0; i < 16; i++) {
        const int idx = tid + i * 128;      // 0..2047
        const int r = idx >> 5;
        const int c = (idx & 31) << 2;
        const float4 v = *(const float4*)&qkv[base + (size_t)(q0 + r) * QKV_LD
                                              + h * HEAD_DIM + c];
        float* dst = &sm[r * AQ_LD + c];
        dst[0] = tf32r(v.x * qscale);
        dst[1] = tf32r(v.y * qscale);
        dst[2] = tf32r(v.z * qscale);
        dst[3] = tf32r(v.w * qscale);
    }
    __syncthreads();

    uint32_t Qf[16][4];
    {
        const uint32_t qa_addr0 = sb
            + ((uint32_t)(wrow + (lm & 1) * 8 + lj) * AQ_LD + (lm >> 1) * 4) * 4u;
        #pragma unroll
        for (int kt = 0; kt < 16; kt++)
            LDSM_X4(Qf[kt], qa_addr0 + (uint32_t)(kt * 8) * 4u);
    }
    __syncthreads();   // KV region free now

    const uint32_t pa_addr0 = Psb
        + ((uint32_t)(wrow + (lm & 1) * 8 + lj) * AP_LD + (lm >> 1) * 4) * 4u;
    const uint32_t kb_addr0 = sb
        + ((uint32_t)((lm >> 1) * 8 + lj) * AK_LD + (lm & 1) * 4) * 4u;
    const float* Vst = sm + 64 * AK_LD;

    // separate K / V cp.async commit groups (64 rows x 32 quads each)
    auto issueK = [&](int jb) {
        const int k0 = jb * 64;
        #pragma unroll
        for (int i = 0; i < 16; i++) {
            const int idx = tid + i * 128;
            const int r = idx >> 5;
            const int c4 = (idx & 31) * 4;
            cp16(sb + (uint32_t)(r * AK_LD + c4) * 4u,
                 &qkv[base + (size_t)(k0 + r) * QKV_LD + DIM + h * HEAD_DIM + c4]);
        }
        CP_COMMIT();
    };
    auto issueV = [&](int jb) {
        const int k0 = jb * 64;
        const uint32_t Vb = sb + (uint32_t)(64 * AK_LD) * 4u;
        #pragma unroll
        for (int i = 0; i < 16; i++) {
            const int idx = tid + i * 128;
            const int r = idx >> 5;
            const int c4 = (idx & 31) * 4;
            cp16(Vb + (uint32_t)(r * AV_LD + c4) * 4u,
                 &qkv[base + (size_t)(k0 + r) * QKV_LD + 2 * DIM + h * HEAD_DIM + c4]);
        }
        CP_COMMIT();
    };

    float mreg[2] = {-1e5f, -1e5f};
    float lreg[2] = {0.0f, 0.0f};
    float O[16][4];
    #pragma unroll
    for (int nt = 0; nt < 16; nt++)
        #pragma unroll
        for (int j = 0; j < 4; j++) O[nt][j] = 0.0f;

    const int ntiles = qb + 1;

    // prologue loads: K(0) then V(0); wait K(0) (V(0) still in flight)
    issueK(0);
    issueV(0);
    CP_WAIT(1);
    __syncthreads();

    for (int jb = 0; jb < ntiles; jb++) {
        const int k0 = jb * 64;
        const bool more = (jb + 1 < ntiles);

        // ---- S = Q K^T  (K region valid; V(jb) streaming in background) ----
        float sreg[8][4];
        #pragma unroll
        for (int nt = 0; nt < 8; nt++)
            #pragma unroll
            for (int j = 0; j < 4; j++) sreg[nt][j] = 0.0f;

        #pragma unroll
        for (int kt = 0; kt < 16; kt++) {
            uint32_t bk[4][4];
            #pragma unroll
            for (int np = 0; np < 4; np++)
                LDSM_X4(bk[np], kb_addr0
                        + (uint32_t)(np * 16 * AK_LD + kt * 8) * 4u);
            #pragma unroll
            for (int np = 0; np < 4; np++) {
                MMA_TF32(sreg[2 * np],     Qf[kt], &bk[np][0]);
                MMA_TF32(sreg[2 * np + 1], Qf[kt], &bk[np][2]);
            }
        }

        __syncthreads();                  // (A) all warps done reading K
        if (more) issueK(jb + 1);         // K load overlaps softmax + PV

        // ---- online softmax (registers only) ----
        const bool need_mask = (jb == qb);
        #pragma unroll
        for (int hh = 0; hh < 2; hh++) {
            const int row = q0 + wrow + g + hh * 8;
            if (need_mask) {
                #pragma unroll
                for (int nt = 0; nt < 8; nt++) {
                    const int col = k0 + nt * 8 + 2 * q;
                    if (col > row)     sreg[nt][2 * hh]     = -1e30f;
                    if (col + 1 > row) sreg[nt][2 * hh + 1] = -1e30f;
                }
            }
            float rmax = -1e30f;
            #pragma unroll
            for (int nt = 0; nt < 8; nt++)
                rmax = fmaxf(rmax, fmaxf(sreg[nt][2 * hh], sreg[nt][2 * hh + 1]));
            rmax = fmaxf(rmax, __shfl_xor_sync(0xffffffffu, rmax, 1));
            rmax = fmaxf(rmax, __shfl_xor_sync(0xffffffffu, rmax, 2));

            const float mnew = fmaxf(mreg[hh], rmax);
            const float corr = fexp2(mreg[hh] - mnew);
            float rsum = 0.0f;
            #pragma unroll
            for (int nt = 0; nt < 8; nt++) {
                const float p0 = fexp2(sreg[nt][2 * hh]     - mnew);
                const float p1 = fexp2(sreg[nt][2 * hh + 1] - mnew);
                sreg[nt][2 * hh] = p0;
                sreg[nt][2 * hh + 1] = p1;
                rsum += p0 + p1;
            }
            rsum += __shfl_xor_sync(0xffffffffu, rsum, 1);
            rsum += __shfl_xor_sync(0xffffffffu, rsum, 2);
            lreg[hh] = lreg[hh] * corr + rsum;
            mreg[hh] = mnew;
            #pragma unroll
            for (int nt2 = 0; nt2 < 16; nt2++) {
                O[nt2][2 * hh] *= corr;
                O[nt2][2 * hh + 1] *= corr;
            }
            #pragma unroll
            for (int nt = 0; nt < 8; nt++) {
                float2 pv = make_float2(tf32r(sreg[nt][2 * hh]),
                                        tf32r(sreg[nt][2 * hh + 1]));
                *(float2*)&Ps[(wrow + g + hh * 8) * AP_LD + nt * 8 + 2 * q] = pv;
            }
        }
        __syncwarp();

        // ---- wait for V(jb): FIFO leaves K(jb+1) pending ----
        if (more) { CP_WAIT(1); } else { CP_WAIT(0); }
        __syncthreads();                  // (B) V visible to all warps

        // ---- O += P V ----
        #pragma unroll
        for (int kt2 = 0; kt2 < 8; kt2++) {
            uint32_t a[4];
            LDSM_X4(a, pa_addr0 + (uint32_t)(kt2 * 8) * 4u);
            #pragma unroll
            for (int nt2 = 0; nt2 < 16; nt2++) {
                uint32_t bfr[2];
                const float* vp = &Vst[(kt2 * 8 + q) * AV_LD + nt2 * 8 + g];
                bfr[0] = __float_as_uint(vp[0]);
                bfr[1] = __float_as_uint(vp[4 * AV_LD]);
                MMA_TF32(O[nt2], a, bfr);
            }
        }

        if (more) {
            __syncthreads();              // (C) all warps done reading V
            issueV(jb + 1);               // V load overlaps next tile's S
            CP_WAIT(1);                   // K(jb+1) done (V(jb+1) pending)
            __syncthreads();              // (D) K visible to all warps
        }
    }

    // epilogue: normalize + store (tf32-rounded; feeds out-proj GEMM)
    #pragma unroll
    for (int hh = 0; hh < 2; hh++) {
        const float inv = 1.0f / lreg[hh];
        const int row = q0 + wrow + g + hh * 8;
        float* orow = out + ((size_t)(b * SEQ + row)) * DIM + h * HEAD_DIM;
        #pragma unroll
        for (int nt2 = 0; nt2 < 16; nt2++) {
            float2 v = make_float2(tf32r(O[nt2][2 * hh] * inv),
                                   tf32r(O[nt2][2 * hh + 1] * inv));
            *(float2*)&orow[nt2 * 8 + 2 * q] = v;
        }
    }
}

// ----------------------------------------------------------------------------
// Launch
// ----------------------------------------------------------------------------
extern "C" void kernel_launch(void* const* d_in, const int* in_sizes, int n_in,
                              void* d_out, int out_size)
{
    const float* x     = (const float*)d_in[0];
    const float* w_qkv = (const float*)d_in[1];
    const float* w_out = (const float*)d_in[2];
    const float* g1    = (const float*)d_in[3];
    const float* g2    = (const float*)d_in[4];
    const float* w1    = (const float*)d_in[5];
    const float* w3    = (const float*)d_in[6];
    const float* w2    = (const float*)d_in[7];
    float* out = (float*)d_out;

    float *xn, *qkvb, *attnb, *x1, *h;
    float *wTqkv, *wTout, *wT13, *wT2;
    cudaGetSymbolAddress((void**)&xn,    g_xn);
    cudaGetSymbolAddress((void**)&qkvb,  g_qkv);
    cudaGetSymbolAddress((void**)&attnb, g_attn);
    cudaGetSymbolAddress((void**)&x1,    g_x1);
    cudaGetSymbolAddress((void**)&h,     g_h);
    cudaGetSymbolAddress((void**)&wTqkv, g_wTqkv);
    cudaGetSymbolAddress((void**)&wTout, g_wTout);
    cudaGetSymbolAddress((void**)&wT13,  g_wT13);
    cudaGetSymbolAddress((void**)&wT2,   g_wT2);

    cudaFuncSetAttribute(attn_mma_kernel,
                         cudaFuncAttributeMaxDynamicSharedMemorySize, ATTN3_SMEM);
    cudaFuncSetAttribute(mma_gemm<0,0>,
                         cudaFuncAttributeMaxDynamicSharedMemorySize, GEMM_SMEM);
    cudaFuncSetAttribute(mma_gemm<1,0>,
                         cudaFuncAttributeMaxDynamicSharedMemorySize, GEMM_SMEM);
    cudaFuncSetAttribute(mma_gemm<0,1>,
                         cudaFuncAttributeMaxDynamicSharedMemorySize, GEMM_SMEM);

    transpose_kernel<<<dim3(QKV_LD / 32, DIM / 32), 256>>>(w_qkv, wTqkv, DIM, QKV_LD, 1, 0);
    rmsnorm_kernel<<<TOKENS, 256>>>(x, g1, xn);
    mma_gemm<0,0><<<(QKV_LD / 128) * (TOKENS / 128), 256, GEMM_SMEM>>>(
        xn, wTqkv, (const float*)0, qkvb, TOKENS, QKV_LD, DIM);
    attn_mma_kernel<<<dim3(SEQ / 64, NHEAD, BATCH), 128, ATTN3_SMEM>>>(qkvb, attnb);
    transpose_kernel<<<dim3(DIM / 32, DIM / 32), 256>>>(w_out, wTout, DIM, DIM, 1, 0);
    mma_gemm<1,0><<<(DIM / 128) * (TOKENS / 128), 256, GEMM_SMEM>>>(
        attnb, wTout, x, x1, TOKENS, DIM, DIM);
    rmsnorm_kernel<<<TOKENS, 256>>>(x1, g2, xn);
    transpose_kernel<<<dim3(FF / 32, DIM / 32), 256>>>(w1, wT13, DIM, FF, 2, 0);
    transpose_kernel<<<dim3(FF / 32, DIM / 32), 256>>>(w3, wT13, DIM, FF, 2, 1);
    mma_gemm<0,1><<<(2 * FF / 128) * (TOKENS / 128), 256, GEMM_SMEM>>>(
        xn, wT13, (const float*)0, h, TOKENS, 2 * FF, DIM);
    transpose_kernel<<<dim3(DIM / 32, FF / 32), 256>>>(w2, wT2, FF, DIM, 1, 0);
    mma_gemm<1,0><<<(DIM / 128) * (TOKENS / 128), 256, GEMM_SMEM>>>(
        h, wT2, x1, out, TOKENS, DIM, FF);
}